// round 4
// baseline (speedup 1.0000x reference)
#include <cuda_runtime.h>
#include <cuda_fp16.h>

#define N_NODES_C 100000
#define D_C 64

typedef unsigned long long ull;

// Y = X @ W in fp16, plus one extra all-zero row (index N_NODES_C) used as a
// safe target for out-of-range edge slots in K2 (predicate-free inner loop).
__device__ __half g_Yh[(size_t)(N_NODES_C + 1) * D_C];

// ---------------------------------------------------------------------------
// Packed f32x2 helpers (Blackwell FFMA2/FADD2 — only reachable via PTX)
// ---------------------------------------------------------------------------
__device__ __forceinline__ ull pack2(float x, float y) {
    ull r; asm("mov.b64 %0, {%1, %2};" : "=l"(r) : "f"(x), "f"(y)); return r;
}
__device__ __forceinline__ void unpack2(ull v, float& x, float& y) {
    asm("mov.b64 {%0, %1}, %2;" : "=f"(x), "=f"(y) : "l"(v));
}
__device__ __forceinline__ ull ffma2(ull a, ull b, ull c) {
    ull d; asm("fma.rn.f32x2 %0, %1, %2, %3;" : "=l"(d) : "l"(a), "l"(b), "l"(c));
    return d;
}
__device__ __forceinline__ ull fadd2(ull a, ull b) {
    ull d; asm("add.rn.f32x2 %0, %1, %2;" : "=l"(d) : "l"(a), "l"(b));
    return d;
}

// ---------------------------------------------------------------------------
// K1: Y[M,64] = X[M,64] @ W[64,64] (fp32 math via FFMA2, fp16 out)
// 128 threads, block tile 128m x 64n, thread tile 8m x 8n (4 m-pairs).
// Per k: 2 LDS.128 (a) + 4 LDS.128 (b) feed 32 FFMA2  -> FMA-issue bound.
// W stored as duplicated pairs {w,w} in a swizzle so each b-load is a
// conflict-free 128B warp transaction.
// ---------------------------------------------------------------------------
#define TM1 128
#define XSTR 132                       // floats; mult of 4 (16B-aligned LDS.128)
#define SMEM_K1 (64 * XSTR * 4 + 64 * 64 * 8)

__global__ __launch_bounds__(128)
void gemm_xw_v3(const float* __restrict__ X,
                const float* __restrict__ W,
                __half* __restrict__ Y,
                int M)
{
    extern __shared__ char sm[];
    float* xs  = (float*)sm;                    // [64][XSTR], transposed: [k][m]
    ull*   ws2 = (ull*)(sm + 64 * XSTR * 4);    // [64][64] swizzled {w,w} pairs

    const int t  = threadIdx.x;
    const int m0 = blockIdx.x * TM1;

    // W -> dup pairs; slot(n) = ((n&7)>>1)*16 + (n>>3)*2 + (n&1)
    #pragma unroll
    for (int i = 0; i < 32; i++) {
        int idx = t + i * 128;                  // k*64 + n
        int k = idx >> 6, n = idx & 63;
        float w = W[idx];
        int slot = ((n & 7) >> 1) * 16 + (n >> 3) * 2 + (n & 1);
        ws2[k * 64 + slot] = pack2(w, w);
    }

    // X tile -> xs[k][m] (zero-fill rows >= M, incl. the zero row M..)
    #pragma unroll
    for (int i = 0; i < 16; i++) {
        int idx = t + i * 128;                  // float4 index
        int m  = idx >> 4;
        int k4 = idx & 15;
        float4 v = make_float4(0.f, 0.f, 0.f, 0.f);
        if (m0 + m < M)
            v = ((const float4*)X)[(size_t)(m0 + m) * 16 + k4];
        xs[(k4 * 4 + 0) * XSTR + m] = v.x;
        xs[(k4 * 4 + 1) * XSTR + m] = v.y;
        xs[(k4 * 4 + 2) * XSTR + m] = v.z;
        xs[(k4 * 4 + 3) * XSTR + m] = v.w;
    }
    __syncthreads();

    const int tx = t & 7;      // n-group: cols tx*8 .. tx*8+7
    const int ty = t >> 3;     // m-group: rows mb .. mb+7
    const int mb = ty * 8;

    ull acc[4][8];             // [m-pair][local col]
    #pragma unroll
    for (int i = 0; i < 4; i++)
        #pragma unroll
        for (int j = 0; j < 8; j++)
            acc[i][j] = 0ull;

    #pragma unroll 4
    for (int k = 0; k < 64; k++) {
        ulonglong2 a01 = *(const ulonglong2*)(xs + k * XSTR + mb);
        ulonglong2 a23 = *(const ulonglong2*)(xs + k * XSTR + mb + 4);
        ull A0 = a01.x, A1 = a01.y, A2 = a23.x, A3 = a23.y;

        const ull* bb = ws2 + k * 64 + tx * 2;
        ulonglong2 b01 = *(const ulonglong2*)(bb + 0);
        ulonglong2 b23 = *(const ulonglong2*)(bb + 16);
        ulonglong2 b45 = *(const ulonglong2*)(bb + 32);
        ulonglong2 b67 = *(const ulonglong2*)(bb + 48);
        ull B[8] = { b01.x, b01.y, b23.x, b23.y, b45.x, b45.y, b67.x, b67.y };

        #pragma unroll
        for (int j = 0; j < 8; j++) {
            acc[0][j] = ffma2(A0, B[j], acc[0][j]);
            acc[1][j] = ffma2(A1, B[j], acc[1][j]);
            acc[2][j] = ffma2(A2, B[j], acc[2][j]);
            acc[3][j] = ffma2(A3, B[j], acc[3][j]);
        }
    }

    // Epilogue: m-pair mp -> rows (m0+mb+2mp, +1), cols tx*8..tx*8+7, fp16
    #pragma unroll
    for (int mp = 0; mp < 4; mp++) {
        int r = m0 + mb + 2 * mp;
        float lo[8], hi[8];
        #pragma unroll
        for (int j = 0; j < 8; j++) unpack2(acc[mp][j], lo[j], hi[j]);
        if (r <= M) {               // rows M (zero row) included
            __half2 h0 = __floats2half2_rn(lo[0], lo[1]);
            __half2 h1 = __floats2half2_rn(lo[2], lo[3]);
            __half2 h2 = __floats2half2_rn(lo[4], lo[5]);
            __half2 h3 = __floats2half2_rn(lo[6], lo[7]);
            uint4 u = make_uint4(*(unsigned*)&h0, *(unsigned*)&h1,
                                 *(unsigned*)&h2, *(unsigned*)&h3);
            *(uint4*)(Y + (size_t)r * 64 + tx * 8) = u;
        }
        if (r + 1 <= M) {
            __half2 h0 = __floats2half2_rn(hi[0], hi[1]);
            __half2 h1 = __floats2half2_rn(hi[2], hi[3]);
            __half2 h2 = __floats2half2_rn(hi[4], hi[5]);
            __half2 h3 = __floats2half2_rn(hi[6], hi[7]);
            uint4 u = make_uint4(*(unsigned*)&h0, *(unsigned*)&h1,
                                 *(unsigned*)&h2, *(unsigned*)&h3);
            *(uint4*)(Y + (size_t)(r + 1) * 64 + tx * 8) = u;
        }
    }
}

// ---------------------------------------------------------------------------
// K2: out[i] = sum_{e in [rp[i],rp[i+1])} Yh[ci[e]]
// Warp per row. 32 edge indices prefetched with ONE coalesced LDG and
// distributed via shfl; out-of-range slots point at the zero row so the
// inner loop has no predication. 4 gathers (LDG.128) in flight per lane.
// fp16 depth-2 pair tree (4 edges) then f32x2 accumulate.
// ---------------------------------------------------------------------------
__global__ __launch_bounds__(256)
void spmm_agg_v3(const __half* __restrict__ Y,
                 const int* __restrict__ rp,
                 const int* __restrict__ ci,
                 float* __restrict__ out)
{
    const int row = blockIdx.x * 8 + (threadIdx.x >> 5);
    if (row >= N_NODES_C) return;
    const int lane = threadIdx.x & 31;
    const int g   = lane >> 3;     // edge subgroup 0..3
    const int sub = lane & 7;      // 16B chunk of the 128B fp16 row

    const int s = __ldg(rp + row);
    const int e = __ldg(rp + row + 1);
    const int cnt = e - s;

    const uint4* __restrict__ base = (const uint4*)Y;

    ull acc2[4] = {0ull, 0ull, 0ull, 0ull};   // 8 f32 as 4 packed pairs

    for (int b0 = 0; b0 < cnt; b0 += 32) {
        int p  = s + b0 + lane;
        int pi = (p < e) ? __ldg(ci + p) : N_NODES_C;   // zero row if OOB
        int lim = cnt - b0;

        #pragma unroll
        for (int h = 0; h < 2; h++) {
            int off = h * 16;
            if (off >= lim) break;                      // warp-uniform
            int c0 = __shfl_sync(0xffffffffu, pi, off + g);
            int c1 = __shfl_sync(0xffffffffu, pi, off + g + 4);
            int c2 = __shfl_sync(0xffffffffu, pi, off + g + 8);
            int c3 = __shfl_sync(0xffffffffu, pi, off + g + 12);
            uint4 v0 = __ldg(base + (size_t)c0 * 8 + sub);
            uint4 v1 = __ldg(base + (size_t)c1 * 8 + sub);
            uint4 v2 = __ldg(base + (size_t)c2 * 8 + sub);
            uint4 v3 = __ldg(base + (size_t)c3 * 8 + sub);
            const __half2* h0 = (const __half2*)&v0;
            const __half2* h1 = (const __half2*)&v1;
            const __half2* h2 = (const __half2*)&v2;
            const __half2* h3 = (const __half2*)&v3;
            #pragma unroll
            for (int i = 0; i < 4; i++) {
                __half2 s01 = __hadd2(h0[i], h1[i]);
                __half2 s23 = __hadd2(h2[i], h3[i]);
                __half2 sall = __hadd2(s01, s23);
                float2 f = __half22float2(sall);
                acc2[i] = fadd2(acc2[i], pack2(f.x, f.y));
            }
        }
    }

    // Reduce the 4 edge subgroups (lanes xor 8, xor 16 share the same sub)
    float a[8];
    #pragma unroll
    for (int i = 0; i < 4; i++) unpack2(acc2[i], a[2 * i], a[2 * i + 1]);
    #pragma unroll
    for (int j = 0; j < 8; j++) {
        a[j] += __shfl_xor_sync(0xffffffffu, a[j], 8);
        a[j] += __shfl_xor_sync(0xffffffffu, a[j], 16);
    }

    if (lane < 8) {
        float* op = out + (size_t)row * 64 + sub * 8;
        *(float4*)(op + 0) = make_float4(a[0], a[1], a[2], a[3]);
        *(float4*)(op + 4) = make_float4(a[4], a[5], a[6], a[7]);
    }
}

// ---------------------------------------------------------------------------
// kernel_launch
// Inputs: 0=X [100000,64] f32, 1=weights [64,64] f32, 2=row_pointers [100001] i32,
//         3=column_index [1600000] i32, 4..6 unused metadata.
// ---------------------------------------------------------------------------
extern "C" void kernel_launch(void* const* d_in, const int* in_sizes, int n_in,
                              void* d_out, int out_size)
{
    const float* X  = (const float*)d_in[0];
    const float* W  = (const float*)d_in[1];
    const int*   rp = (const int*)d_in[2];
    const int*   ci = (const int*)d_in[3];
    float*       out = (float*)d_out;

    const int M = in_sizes[0] / D_C;   // 100000

    __half* Y;
    cudaGetSymbolAddress((void**)&Y, g_Yh);

    cudaFuncSetAttribute(gemm_xw_v3, cudaFuncAttributeMaxDynamicSharedMemorySize, SMEM_K1);
    {
        dim3 grid((M + TM1 - 1) / TM1);
        gemm_xw_v3<<<grid, 128, SMEM_K1>>>(X, W, Y, M);
    }
    {
        dim3 grid((M + 7) / 8);
        spmm_agg_v3<<<grid, 256>>>(Y, rp, ci, out);
    }
}

// round 6
// speedup vs baseline: 1.4544x; 1.4544x over previous
#include <cuda_runtime.h>
#include <cuda_fp16.h>
#include <cstdint>

#define N_NODES_C 100000
#define D_C 64

typedef unsigned long long ull;

// Y = X @ W in fp16, plus one extra all-zero row (index N_NODES_C) used as a
// safe target for out-of-range edge slots in K2 (predicate-free inner loop).
__device__ __half g_Yh[(size_t)(N_NODES_C + 1) * D_C];

// ---------------------------------------------------------------------------
// helpers
// ---------------------------------------------------------------------------
__device__ __forceinline__ ull pack2(float x, float y) {
    ull r; asm("mov.b64 %0, {%1, %2};" : "=l"(r) : "f"(x), "f"(y)); return r;
}
__device__ __forceinline__ void unpack2(ull v, float& x, float& y) {
    asm("mov.b64 {%0, %1}, %2;" : "=f"(x), "=f"(y) : "l"(v));
}
__device__ __forceinline__ ull fadd2(ull a, ull b) {
    ull d; asm("add.rn.f32x2 %0, %1, %2;" : "=l"(d) : "l"(a), "l"(b));
    return d;
}
__device__ __forceinline__ uint32_t f2tf32(float f) {
    uint32_t r; asm("cvt.rna.tf32.f32 %0, %1;" : "=r"(r) : "f"(f)); return r;
}
__device__ __forceinline__ void mma_tf32(float* d,
                                         uint32_t a0, uint32_t a1, uint32_t a2, uint32_t a3,
                                         uint32_t b0, uint32_t b1) {
    asm volatile(
        "mma.sync.aligned.m16n8k8.row.col.f32.tf32.tf32.f32 "
        "{%0,%1,%2,%3}, {%4,%5,%6,%7}, {%8,%9}, {%0,%1,%2,%3};"
        : "+f"(d[0]), "+f"(d[1]), "+f"(d[2]), "+f"(d[3])
        : "r"(a0), "r"(a1), "r"(a2), "r"(a3), "r"(b0), "r"(b1));
}

// ---------------------------------------------------------------------------
// K1: Y[M,64] = X[M,64] @ W[64,64] via tf32 tensor-core MMA, fp16 output.
// 256 threads = 8 warps; block tile 128m x 64n; each warp 16m x 64n.
// Padded smem strides (XPAD=68, WPAD=72) make every fragment load a
// conflict-free 32-bank access. Memory-bound: 25.6MB read + 12.8MB write.
// ---------------------------------------------------------------------------
#define XPAD 68
#define WPAD 72
#define SMEM_GEMM ((128 * XPAD + 64 * WPAD) * 4)   // 53,248 B

__global__ __launch_bounds__(256)
void gemm_tf32(const float* __restrict__ X,
               const float* __restrict__ W,
               __half* __restrict__ Y,
               int M)
{
    extern __shared__ uint32_t sm4[];
    uint32_t* xs = sm4;                 // [128][XPAD] tf32 bits
    uint32_t* ws = sm4 + 128 * XPAD;    // [64][WPAD]  tf32 bits

    const int t  = threadIdx.x;
    const int m0 = blockIdx.x * 128;

    // W -> smem (tf32-rounded)
    #pragma unroll
    for (int i = 0; i < 16; i++) {
        int idx = t + i * 256;              // k*64 + n
        int k = idx >> 6, n = idx & 63;
        ws[k * WPAD + n] = f2tf32(W[idx]);
    }

    // X tile -> smem (tf32-rounded, zero-fill rows >= M incl. zero row)
    #pragma unroll
    for (int i = 0; i < 8; i++) {
        int idx = t + i * 256;              // float4 index
        int m  = idx >> 4;
        int c4 = idx & 15;
        float4 v = make_float4(0.f, 0.f, 0.f, 0.f);
        if (m0 + m < M)
            v = ((const float4*)X)[(size_t)(m0 + m) * 16 + c4];
        uint32_t* p = xs + m * XPAD + c4 * 4;
        p[0] = f2tf32(v.x); p[1] = f2tf32(v.y);
        p[2] = f2tf32(v.z); p[3] = f2tf32(v.w);
    }
    __syncthreads();

    const int warp = t >> 5;
    const int lane = t & 31;
    const int g  = lane >> 2;      // group id (row within 8)
    const int tg = lane & 3;       // thread in group (col within 4)
    const int mrow = warp * 16;

    float acc[8][4];
    #pragma unroll
    for (int j = 0; j < 8; j++)
        #pragma unroll
        for (int c = 0; c < 4; c++) acc[j][c] = 0.f;

    #pragma unroll
    for (int ks = 0; ks < 8; ks++) {
        const int k0 = ks * 8;
        uint32_t a0 = xs[(mrow + g)     * XPAD + k0 + tg];
        uint32_t a1 = xs[(mrow + g + 8) * XPAD + k0 + tg];
        uint32_t a2 = xs[(mrow + g)     * XPAD + k0 + tg + 4];
        uint32_t a3 = xs[(mrow + g + 8) * XPAD + k0 + tg + 4];
        #pragma unroll
        for (int j = 0; j < 8; j++) {
            uint32_t b0 = ws[(k0 + tg)     * WPAD + j * 8 + g];
            uint32_t b1 = ws[(k0 + tg + 4) * WPAD + j * 8 + g];
            mma_tf32(acc[j], a0, a1, a2, a3, b0, b1);
        }
    }

    // Epilogue: thread owns rows (m0+mrow+g, +8), cols {j*8+2tg, +1}, fp16.
    const int r0 = m0 + mrow + g;
    const int r1 = r0 + 8;
    #pragma unroll
    for (int j = 0; j < 8; j++) {
        int col = j * 8 + 2 * tg;
        __half2 lo = __floats2half2_rn(acc[j][0], acc[j][1]);
        __half2 hi = __floats2half2_rn(acc[j][2], acc[j][3]);
        if (r0 <= M) *(__half2*)(Y + (size_t)r0 * 64 + col) = lo;
        if (r1 <= M) *(__half2*)(Y + (size_t)r1 * 64 + col) = hi;
    }
}

// ---------------------------------------------------------------------------
// K2: out[i] = sum_{e in [rp[i],rp[i+1])} Yh[ci[e]]   (fp32 accumulation)
// One warp per row, 128-thread blocks. 4 lane-groups of 8; per step each
// group handles 4 edges -> 16 edges/warp/step, 4 independent LDG.128 gathers
// in flight per lane. Index loads are clamped in-bounds (min) and OOB slots
// select the zero row: no predication, no shfl on the critical path.
// fp16 depth-2 pair tree then packed f32x2 accumulate.
// ---------------------------------------------------------------------------
__global__ __launch_bounds__(128)
void spmm_agg_v4(const __half* __restrict__ Y,
                 const int* __restrict__ rp,
                 const int* __restrict__ ci,
                 float* __restrict__ out)
{
    const int row = blockIdx.x * 4 + (threadIdx.x >> 5);
    if (row >= N_NODES_C) return;
    const int lane = threadIdx.x & 31;
    const int g   = lane >> 3;     // edge subgroup 0..3
    const int sub = lane & 7;      // 16B chunk of the 128B fp16 row

    const int s = __ldg(rp + row);
    const int e = __ldg(rp + row + 1);

    const uint4* __restrict__ base = (const uint4*)Y;

    ull acc2[4] = {0ull, 0ull, 0ull, 0ull};   // 8 f32 as packed pairs

    for (int k = s; k < e; k += 16) {
        int i0 = k + g;
        int i1 = k + g + 4;
        int i2 = k + g + 8;
        int i3 = k + g + 12;
        int ec = e - 1;
        // in-bounds clamped loads; OOB slots -> zero row
        int c0 = __ldg(ci + min(i0, ec)); c0 = (i0 < e) ? c0 : N_NODES_C;
        int c1 = __ldg(ci + min(i1, ec)); c1 = (i1 < e) ? c1 : N_NODES_C;
        int c2 = __ldg(ci + min(i2, ec)); c2 = (i2 < e) ? c2 : N_NODES_C;
        int c3 = __ldg(ci + min(i3, ec)); c3 = (i3 < e) ? c3 : N_NODES_C;

        uint4 v0 = __ldg(base + (size_t)c0 * 8 + sub);
        uint4 v1 = __ldg(base + (size_t)c1 * 8 + sub);
        uint4 v2 = __ldg(base + (size_t)c2 * 8 + sub);
        uint4 v3 = __ldg(base + (size_t)c3 * 8 + sub);

        const __half2* h0 = (const __half2*)&v0;
        const __half2* h1 = (const __half2*)&v1;
        const __half2* h2 = (const __half2*)&v2;
        const __half2* h3 = (const __half2*)&v3;
        #pragma unroll
        for (int i = 0; i < 4; i++) {
            __half2 s01 = __hadd2(h0[i], h1[i]);
            __half2 s23 = __hadd2(h2[i], h3[i]);
            __half2 sall = __hadd2(s01, s23);
            float2 f = __half22float2(sall);
            acc2[i] = fadd2(acc2[i], pack2(f.x, f.y));
        }
    }

    // Reduce the 4 edge subgroups (lanes xor 8, xor 16 share the same sub)
    float a[8];
    #pragma unroll
    for (int i = 0; i < 4; i++) unpack2(acc2[i], a[2 * i], a[2 * i + 1]);
    #pragma unroll
    for (int j = 0; j < 8; j++) {
        a[j] += __shfl_xor_sync(0xffffffffu, a[j], 8);
        a[j] += __shfl_xor_sync(0xffffffffu, a[j], 16);
    }

    if (lane < 8) {
        float* op = out + (size_t)row * 64 + sub * 8;
        *(float4*)(op + 0) = make_float4(a[0], a[1], a[2], a[3]);
        *(float4*)(op + 4) = make_float4(a[4], a[5], a[6], a[7]);
    }
}

// ---------------------------------------------------------------------------
// kernel_launch
// Inputs: 0=X [100000,64] f32, 1=weights [64,64] f32, 2=row_pointers [100001] i32,
//         3=column_index [1600000] i32, 4..6 unused metadata.
// ---------------------------------------------------------------------------
extern "C" void kernel_launch(void* const* d_in, const int* in_sizes, int n_in,
                              void* d_out, int out_size)
{
    const float* X  = (const float*)d_in[0];
    const float* W  = (const float*)d_in[1];
    const int*   rp = (const int*)d_in[2];
    const int*   ci = (const int*)d_in[3];
    float*       out = (float*)d_out;

    const int M = in_sizes[0] / D_C;   // 100000

    __half* Y;
    cudaGetSymbolAddress((void**)&Y, g_Yh);

    cudaFuncSetAttribute(gemm_tf32, cudaFuncAttributeMaxDynamicSharedMemorySize, SMEM_GEMM);
    {
        // grid covers rows 0..M inclusive (row M is the zero row)
        dim3 grid((M + 128) / 128);
        gemm_tf32<<<grid, 256, SMEM_GEMM>>>(X, W, Y, M);
    }
    {
        dim3 grid((M + 3) / 4);
        spmm_agg_v4<<<grid, 128>>>(Y, rp, ci, out);
    }
}

// round 7
// speedup vs baseline: 1.5228x; 1.0471x over previous
#include <cuda_runtime.h>
#include <cuda_fp16.h>
#include <cstdint>

#define N_NODES_C 100000
#define D_C 64
#define ROWS_PER_WARP 8

typedef unsigned long long ull;

// Y = X @ W in fp16, plus one extra all-zero row (index N_NODES_C) used as a
// safe target for out-of-range edge slots in K2 (predicate-free inner loop).
__device__ __half g_Yh[(size_t)(N_NODES_C + 1) * D_C];

// ---------------------------------------------------------------------------
// helpers
// ---------------------------------------------------------------------------
__device__ __forceinline__ ull pack2(float x, float y) {
    ull r; asm("mov.b64 %0, {%1, %2};" : "=l"(r) : "f"(x), "f"(y)); return r;
}
__device__ __forceinline__ void unpack2(ull v, float& x, float& y) {
    asm("mov.b64 {%0, %1}, %2;" : "=f"(x), "=f"(y) : "l"(v));
}
__device__ __forceinline__ ull fadd2(ull a, ull b) {
    ull d; asm("add.rn.f32x2 %0, %1, %2;" : "=l"(d) : "l"(a), "l"(b));
    return d;
}
__device__ __forceinline__ uint32_t f2tf32(float f) {
    uint32_t r; asm("cvt.rna.tf32.f32 %0, %1;" : "=r"(r) : "f"(f)); return r;
}
__device__ __forceinline__ void mma_tf32(float* d,
                                         uint32_t a0, uint32_t a1, uint32_t a2, uint32_t a3,
                                         uint32_t b0, uint32_t b1) {
    asm volatile(
        "mma.sync.aligned.m16n8k8.row.col.f32.tf32.tf32.f32 "
        "{%0,%1,%2,%3}, {%4,%5,%6,%7}, {%8,%9}, {%0,%1,%2,%3};"
        : "+f"(d[0]), "+f"(d[1]), "+f"(d[2]), "+f"(d[3])
        : "r"(a0), "r"(a1), "r"(a2), "r"(a3), "r"(b0), "r"(b1));
}

// ---------------------------------------------------------------------------
// K1: Y[M,64] = X[M,64] @ W[64,64] via tf32 tensor-core MMA, fp16 output.
// (unchanged from R6 — measured ~9.2us, at its memory floor)
// ---------------------------------------------------------------------------
#define XPAD 68
#define WPAD 72
#define SMEM_GEMM ((128 * XPAD + 64 * WPAD) * 4)   // 53,248 B

__global__ __launch_bounds__(256)
void gemm_tf32(const float* __restrict__ X,
               const float* __restrict__ W,
               __half* __restrict__ Y,
               int M)
{
    extern __shared__ uint32_t sm4[];
    uint32_t* xs = sm4;                 // [128][XPAD] tf32 bits
    uint32_t* ws = sm4 + 128 * XPAD;    // [64][WPAD]  tf32 bits

    const int t  = threadIdx.x;
    const int m0 = blockIdx.x * 128;

    #pragma unroll
    for (int i = 0; i < 16; i++) {
        int idx = t + i * 256;              // k*64 + n
        int k = idx >> 6, n = idx & 63;
        ws[k * WPAD + n] = f2tf32(W[idx]);
    }

    #pragma unroll
    for (int i = 0; i < 8; i++) {
        int idx = t + i * 256;              // float4 index
        int m  = idx >> 4;
        int c4 = idx & 15;
        float4 v = make_float4(0.f, 0.f, 0.f, 0.f);
        if (m0 + m < M)
            v = ((const float4*)X)[(size_t)(m0 + m) * 16 + c4];
        uint32_t* p = xs + m * XPAD + c4 * 4;
        p[0] = f2tf32(v.x); p[1] = f2tf32(v.y);
        p[2] = f2tf32(v.z); p[3] = f2tf32(v.w);
    }
    __syncthreads();

    const int warp = t >> 5;
    const int lane = t & 31;
    const int g  = lane >> 2;
    const int tg = lane & 3;
    const int mrow = warp * 16;

    float acc[8][4];
    #pragma unroll
    for (int j = 0; j < 8; j++)
        #pragma unroll
        for (int c = 0; c < 4; c++) acc[j][c] = 0.f;

    #pragma unroll
    for (int ks = 0; ks < 8; ks++) {
        const int k0 = ks * 8;
        uint32_t a0 = xs[(mrow + g)     * XPAD + k0 + tg];
        uint32_t a1 = xs[(mrow + g + 8) * XPAD + k0 + tg];
        uint32_t a2 = xs[(mrow + g)     * XPAD + k0 + tg + 4];
        uint32_t a3 = xs[(mrow + g + 8) * XPAD + k0 + tg + 4];
        #pragma unroll
        for (int j = 0; j < 8; j++) {
            uint32_t b0 = ws[(k0 + tg)     * WPAD + j * 8 + g];
            uint32_t b1 = ws[(k0 + tg + 4) * WPAD + j * 8 + g];
            mma_tf32(acc[j], a0, a1, a2, a3, b0, b1);
        }
    }

    const int r0 = m0 + mrow + g;
    const int r1 = r0 + 8;
    #pragma unroll
    for (int j = 0; j < 8; j++) {
        int col = j * 8 + 2 * tg;
        __half2 lo = __floats2half2_rn(acc[j][0], acc[j][1]);
        __half2 hi = __floats2half2_rn(acc[j][2], acc[j][3]);
        if (r0 <= M) *(__half2*)(Y + (size_t)r0 * 64 + col) = lo;
        if (r1 <= M) *(__half2*)(Y + (size_t)r1 * 64 + col) = hi;
    }
}

// ---------------------------------------------------------------------------
// K2 v5: out[i] = sum_{e in [rp[i],rp[i+1])} Yh[ci[e]]   (fp32 accumulation)
// Each warp owns 8 CONSECUTIVE rows:
//   - all 9 row pointers fetched with ONE coalesced LDG + shfl (no rp chain)
//   - row j+1's step-0 index loads issued while row j's gathers are in flight
//     (software pipeline: per-row critical path ~= one L2 trip, not two)
//   - rows >16 edges continue in an inline loop (unpipelined, ~37% of rows)
// Index loads clamped to [0, NE-1]; OOB slots select the zero row.
// ---------------------------------------------------------------------------
struct Idx4 { int c0, c1, c2, c3; };

__device__ __forceinline__ Idx4 load_idx4(const int* __restrict__ ci,
                                          int k, int e, int g, int nem1)
{
    Idx4 r;
    int i0 = k + g, i1 = k + g + 4, i2 = k + g + 8, i3 = k + g + 12;
    int a0 = min(i0, nem1), a1 = min(i1, nem1);
    int a2 = min(i2, nem1), a3 = min(i3, nem1);
    r.c0 = __ldg(ci + a0); r.c0 = (i0 < e) ? r.c0 : N_NODES_C;
    r.c1 = __ldg(ci + a1); r.c1 = (i1 < e) ? r.c1 : N_NODES_C;
    r.c2 = __ldg(ci + a2); r.c2 = (i2 < e) ? r.c2 : N_NODES_C;
    r.c3 = __ldg(ci + a3); r.c3 = (i3 < e) ? r.c3 : N_NODES_C;
    return r;
}

__device__ __forceinline__ void accum16(ull* acc2, const uint4* __restrict__ base,
                                        Idx4 c, int sub)
{
    uint4 v0 = __ldg(base + (size_t)c.c0 * 8 + sub);
    uint4 v1 = __ldg(base + (size_t)c.c1 * 8 + sub);
    uint4 v2 = __ldg(base + (size_t)c.c2 * 8 + sub);
    uint4 v3 = __ldg(base + (size_t)c.c3 * 8 + sub);
    const __half2* h0 = (const __half2*)&v0;
    const __half2* h1 = (const __half2*)&v1;
    const __half2* h2 = (const __half2*)&v2;
    const __half2* h3 = (const __half2*)&v3;
    #pragma unroll
    for (int i = 0; i < 4; i++) {
        __half2 s01 = __hadd2(h0[i], h1[i]);
        __half2 s23 = __hadd2(h2[i], h3[i]);
        __half2 sall = __hadd2(s01, s23);
        float2 f = __half22float2(sall);
        acc2[i] = fadd2(acc2[i], pack2(f.x, f.y));
    }
}

__global__ __launch_bounds__(256)
void spmm_agg_v5(const __half* __restrict__ Y,
                 const int* __restrict__ rp,
                 const int* __restrict__ ci,
                 float* __restrict__ out,
                 int n_edges)
{
    const int warp_g = (blockIdx.x * blockDim.x + threadIdx.x) >> 5;
    const int lane = threadIdx.x & 31;
    const int g   = lane >> 3;     // edge subgroup 0..3
    const int sub = lane & 7;      // 16B chunk of the 128B fp16 row
    const int base_row = warp_g * ROWS_PER_WARP;
    if (base_row >= N_NODES_C) return;

    const int nem1 = n_edges - 1;
    const uint4* __restrict__ baseY = (const uint4*)Y;

    // One coalesced load of 9 row pointers for this warp's rows.
    int rpv = __ldg(rp + base_row + min(lane, ROWS_PER_WARP));

    // Pipeline prologue: row 0 bounds + step-0 indices.
    int s = __shfl_sync(0xffffffffu, rpv, 0);
    int e = __shfl_sync(0xffffffffu, rpv, 1);
    Idx4 c = load_idx4(ci, s, e, g, nem1);

    #pragma unroll
    for (int j = 0; j < ROWS_PER_WARP; j++) {
        const int s_cur = s, e_cur = e;

        ull acc2[4] = {0ull, 0ull, 0ull, 0ull};

        // Issue this row's step-0 gathers (indices already in flight/ready).
        uint4 v0 = __ldg(baseY + (size_t)c.c0 * 8 + sub);
        uint4 v1 = __ldg(baseY + (size_t)c.c1 * 8 + sub);
        uint4 v2 = __ldg(baseY + (size_t)c.c2 * 8 + sub);
        uint4 v3 = __ldg(baseY + (size_t)c.c3 * 8 + sub);

        // Prefetch next row's bounds + step-0 indices while gathers fly.
        Idx4 nc;
        if (j + 1 < ROWS_PER_WARP) {
            s = __shfl_sync(0xffffffffu, rpv, j + 1);
            e = __shfl_sync(0xffffffffu, rpv, j + 2);
            nc = load_idx4(ci, s, e, g, nem1);
        }

        // Consume step-0 gathers.
        {
            const __half2* h0 = (const __half2*)&v0;
            const __half2* h1 = (const __half2*)&v1;
            const __half2* h2 = (const __half2*)&v2;
            const __half2* h3 = (const __half2*)&v3;
            #pragma unroll
            for (int i = 0; i < 4; i++) {
                __half2 s01 = __hadd2(h0[i], h1[i]);
                __half2 s23 = __hadd2(h2[i], h3[i]);
                __half2 sall = __hadd2(s01, s23);
                float2 f = __half22float2(sall);
                acc2[i] = fadd2(acc2[i], pack2(f.x, f.y));
            }
        }

        // Continuation for rows longer than 16 edges (unpipelined, rare-ish).
        for (int k = s_cur + 16; k < e_cur; k += 16) {
            Idx4 cc = load_idx4(ci, k, e_cur, g, nem1);
            accum16(acc2, baseY, cc, sub);
        }

        // Reduce the 4 edge subgroups and store row.
        float a[8];
        #pragma unroll
        for (int i = 0; i < 4; i++) unpack2(acc2[i], a[2 * i], a[2 * i + 1]);
        #pragma unroll
        for (int q = 0; q < 8; q++) {
            a[q] += __shfl_xor_sync(0xffffffffu, a[q], 8);
            a[q] += __shfl_xor_sync(0xffffffffu, a[q], 16);
        }
        if (lane < 8) {
            float* op = out + (size_t)(base_row + j) * 64 + sub * 8;
            *(float4*)(op + 0) = make_float4(a[0], a[1], a[2], a[3]);
            *(float4*)(op + 4) = make_float4(a[4], a[5], a[6], a[7]);
        }

        c = nc;
    }
}

// ---------------------------------------------------------------------------
// kernel_launch
// Inputs: 0=X [100000,64] f32, 1=weights [64,64] f32, 2=row_pointers [100001] i32,
//         3=column_index [1600000] i32, 4..6 unused metadata.
// ---------------------------------------------------------------------------
extern "C" void kernel_launch(void* const* d_in, const int* in_sizes, int n_in,
                              void* d_out, int out_size)
{
    const float* X  = (const float*)d_in[0];
    const float* W  = (const float*)d_in[1];
    const int*   rp = (const int*)d_in[2];
    const int*   ci = (const int*)d_in[3];
    float*       out = (float*)d_out;

    const int M = in_sizes[0] / D_C;       // 100000
    const int NE = in_sizes[3];            // 1600000

    __half* Y;
    cudaGetSymbolAddress((void**)&Y, g_Yh);

    cudaFuncSetAttribute(gemm_tf32, cudaFuncAttributeMaxDynamicSharedMemorySize, SMEM_GEMM);
    {
        // grid covers rows 0..M inclusive (row M is the zero row)
        dim3 grid((M + 128) / 128);
        gemm_tf32<<<grid, 256, SMEM_GEMM>>>(X, W, Y, M);
    }
    {
        const int n_warps  = (M + ROWS_PER_WARP - 1) / ROWS_PER_WARP;   // 12500
        const int n_blocks = (n_warps + 7) / 8;                         // 1563
        spmm_agg_v5<<<n_blocks, 256>>>(Y, rp, ci, out, NE);
    }
}

// round 11
// speedup vs baseline: 1.5992x; 1.0502x over previous
#include <cuda_runtime.h>
#include <cuda_fp16.h>
#include <cstdint>

#define N_NODES_C 100000
#define D_C 64
#define ROWS_PER_WARP 8

typedef unsigned long long ull;

// Y = X @ W in fp16, plus one extra all-zero row (index N_NODES_C) used as a
// safe target for out-of-range edge slots in K2 (predicate-free inner loop).
__device__ __half g_Yh[(size_t)(N_NODES_C + 1) * D_C];

// ---------------------------------------------------------------------------
// helpers
// ---------------------------------------------------------------------------
__device__ __forceinline__ ull pack2(float x, float y) {
    ull r; asm("mov.b64 %0, {%1, %2};" : "=l"(r) : "f"(x), "f"(y)); return r;
}
__device__ __forceinline__ void unpack2(ull v, float& x, float& y) {
    asm("mov.b64 {%0, %1}, %2;" : "=f"(x), "=f"(y) : "l"(v));
}
__device__ __forceinline__ ull fadd2(ull a, ull b) {
    ull d; asm("add.rn.f32x2 %0, %1, %2;" : "=l"(d) : "l"(a), "l"(b));
    return d;
}
__device__ __forceinline__ uint32_t f2tf32(float f) {
    uint32_t r; asm("cvt.rna.tf32.f32 %0, %1;" : "=r"(r) : "f"(f)); return r;
}
__device__ __forceinline__ void mma_tf32(float* d,
                                         uint32_t a0, uint32_t a1, uint32_t a2, uint32_t a3,
                                         uint32_t b0, uint32_t b1) {
    asm volatile(
        "mma.sync.aligned.m16n8k8.row.col.f32.tf32.tf32.f32 "
        "{%0,%1,%2,%3}, {%4,%5,%6,%7}, {%8,%9}, {%0,%1,%2,%3};"
        : "+f"(d[0]), "+f"(d[1]), "+f"(d[2]), "+f"(d[3])
        : "r"(a0), "r"(a1), "r"(a2), "r"(a3), "r"(b0), "r"(b1));
}

// ---------------------------------------------------------------------------
// K1: Y[M,64] = X[M,64] @ W[64,64] via tf32 tensor-core MMA, fp16 output.
// (unchanged — measured ~9.2us, at its memory floor)
// ---------------------------------------------------------------------------
#define XPAD 68
#define WPAD 72
#define SMEM_GEMM ((128 * XPAD + 64 * WPAD) * 4)   // 53,248 B

__global__ __launch_bounds__(256)
void gemm_tf32(const float* __restrict__ X,
               const float* __restrict__ W,
               __half* __restrict__ Y,
               int M)
{
    extern __shared__ uint32_t sm4[];
    uint32_t* xs = sm4;                 // [128][XPAD] tf32 bits
    uint32_t* ws = sm4 + 128 * XPAD;    // [64][WPAD]  tf32 bits

    const int t  = threadIdx.x;
    const int m0 = blockIdx.x * 128;

    #pragma unroll
    for (int i = 0; i < 16; i++) {
        int idx = t + i * 256;              // k*64 + n
        int k = idx >> 6, n = idx & 63;
        ws[k * WPAD + n] = f2tf32(W[idx]);
    }

    #pragma unroll
    for (int i = 0; i < 8; i++) {
        int idx = t + i * 256;              // float4 index
        int m  = idx >> 4;
        int c4 = idx & 15;
        float4 v = make_float4(0.f, 0.f, 0.f, 0.f);
        if (m0 + m < M)
            v = ((const float4*)X)[(size_t)(m0 + m) * 16 + c4];
        uint32_t* p = xs + m * XPAD + c4 * 4;
        p[0] = f2tf32(v.x); p[1] = f2tf32(v.y);
        p[2] = f2tf32(v.z); p[3] = f2tf32(v.w);
    }
    __syncthreads();

    const int warp = t >> 5;
    const int lane = t & 31;
    const int g  = lane >> 2;
    const int tg = lane & 3;
    const int mrow = warp * 16;

    float acc[8][4];
    #pragma unroll
    for (int j = 0; j < 8; j++)
        #pragma unroll
        for (int c = 0; c < 4; c++) acc[j][c] = 0.f;

    #pragma unroll
    for (int ks = 0; ks < 8; ks++) {
        const int k0 = ks * 8;
        uint32_t a0 = xs[(mrow + g)     * XPAD + k0 + tg];
        uint32_t a1 = xs[(mrow + g + 8) * XPAD + k0 + tg];
        uint32_t a2 = xs[(mrow + g)     * XPAD + k0 + tg + 4];
        uint32_t a3 = xs[(mrow + g + 8) * XPAD + k0 + tg + 4];
        #pragma unroll
        for (int j = 0; j < 8; j++) {
            uint32_t b0 = ws[(k0 + tg)     * WPAD + j * 8 + g];
            uint32_t b1 = ws[(k0 + tg + 4) * WPAD + j * 8 + g];
            mma_tf32(acc[j], a0, a1, a2, a3, b0, b1);
        }
    }

    const int r0 = m0 + mrow + g;
    const int r1 = r0 + 8;
    #pragma unroll
    for (int j = 0; j < 8; j++) {
        int col = j * 8 + 2 * tg;
        __half2 lo = __floats2half2_rn(acc[j][0], acc[j][1]);
        __half2 hi = __floats2half2_rn(acc[j][2], acc[j][3]);
        if (r0 <= M) *(__half2*)(Y + (size_t)r0 * 64 + col) = lo;
        if (r1 <= M) *(__half2*)(Y + (size_t)r1 * 64 + col) = hi;
    }
}

// ---------------------------------------------------------------------------
// K2 v6b: out[i] = sum_{e in [rp[i],rp[i+1])} Yh[ci[e]]   (fp32 accumulation)
// Warp owns 8 consecutive rows (one coalesced rp load + shfl).
//  - row j+1's window-0 indices prefetched while row j's gathers fly
//  - continuation windows pipelined (window t+1 idx in flight during consume t)
//  - warp-uniform half-window: remaining <= 8 edges -> 2 gathers + half tree
// Index loads clamped to [0, NE-1]; OOB slots select the zero row.
// (v6b: all conditionally-assigned locals zero-initialized — no UB reads)
// ---------------------------------------------------------------------------
struct Idx4 { int c0, c1, c2, c3; };

__device__ __forceinline__ Idx4 load_idx4(const int* __restrict__ ci,
                                          int k, int e, int g, int nem1)
{
    Idx4 r;
    int i0 = k + g, i1 = k + g + 4, i2 = k + g + 8, i3 = k + g + 12;
    r.c0 = __ldg(ci + min(i0, nem1)); r.c0 = (i0 < e) ? r.c0 : N_NODES_C;
    r.c1 = __ldg(ci + min(i1, nem1)); r.c1 = (i1 < e) ? r.c1 : N_NODES_C;
    r.c2 = __ldg(ci + min(i2, nem1)); r.c2 = (i2 < e) ? r.c2 : N_NODES_C;
    r.c3 = __ldg(ci + min(i3, nem1)); r.c3 = (i3 < e) ? r.c3 : N_NODES_C;
    return r;
}

__device__ __forceinline__ void consume_full(ull* acc2, uint4 v0, uint4 v1,
                                             uint4 v2, uint4 v3)
{
    const __half2* h0 = (const __half2*)&v0;
    const __half2* h1 = (const __half2*)&v1;
    const __half2* h2 = (const __half2*)&v2;
    const __half2* h3 = (const __half2*)&v3;
    #pragma unroll
    for (int i = 0; i < 4; i++) {
        __half2 s01 = __hadd2(h0[i], h1[i]);
        __half2 s23 = __hadd2(h2[i], h3[i]);
        __half2 sall = __hadd2(s01, s23);
        float2 f = __half22float2(sall);
        acc2[i] = fadd2(acc2[i], pack2(f.x, f.y));
    }
}

__device__ __forceinline__ void consume_half(ull* acc2, uint4 v0, uint4 v1)
{
    const __half2* h0 = (const __half2*)&v0;
    const __half2* h1 = (const __half2*)&v1;
    #pragma unroll
    for (int i = 0; i < 4; i++) {
        __half2 s01 = __hadd2(h0[i], h1[i]);
        float2 f = __half22float2(s01);
        acc2[i] = fadd2(acc2[i], pack2(f.x, f.y));
    }
}

__global__ __launch_bounds__(128)
void spmm_agg_v6b(const __half* __restrict__ Y,
                  const int* __restrict__ rp,
                  const int* __restrict__ ci,
                  float* __restrict__ out,
                  int n_edges)
{
    const int warp_g = (blockIdx.x * blockDim.x + threadIdx.x) >> 5;
    const int lane = threadIdx.x & 31;
    const int g   = lane >> 3;     // edge subgroup 0..3
    const int sub = lane & 7;      // 16B chunk of the 128B fp16 row
    const int base_row = warp_g * ROWS_PER_WARP;
    if (base_row >= N_NODES_C) return;

    const int nem1 = n_edges - 1;
    const uint4* __restrict__ baseY = (const uint4*)Y;

    // One coalesced load of 9 row pointers for this warp's rows.
    int rpv = __ldg(rp + base_row + min(lane, ROWS_PER_WARP));

    // Pipeline prologue: row 0 bounds + window-0 indices.
    int s = __shfl_sync(0xffffffffu, rpv, 0);
    int e = __shfl_sync(0xffffffffu, rpv, 1);
    Idx4 c = load_idx4(ci, s, e, g, nem1);

    #pragma unroll
    for (int j = 0; j < ROWS_PER_WARP; j++) {
        const int s_cur = s, e_cur = e;
        const int n = e_cur - s_cur;

        ull acc2[4] = {0ull, 0ull, 0ull, 0ull};

        // Window 0: issue gathers (indices already in flight/ready).
        // Warp-uniform: skip upper half if n <= 8.
        const bool big0 = (n > 8);
        uint4 v0 = __ldg(baseY + (size_t)c.c0 * 8 + sub);
        uint4 v1 = __ldg(baseY + (size_t)c.c1 * 8 + sub);
        uint4 v2 = make_uint4(0u, 0u, 0u, 0u);
        uint4 v3 = make_uint4(0u, 0u, 0u, 0u);
        if (big0) {
            v2 = __ldg(baseY + (size_t)c.c2 * 8 + sub);
            v3 = __ldg(baseY + (size_t)c.c3 * 8 + sub);
        }

        // Prefetch next row's bounds + window-0 indices while gathers fly.
        Idx4 nc = c;
        if (j + 1 < ROWS_PER_WARP) {
            s = __shfl_sync(0xffffffffu, rpv, j + 1);
            e = __shfl_sync(0xffffffffu, rpv, j + 2);
            nc = load_idx4(ci, s, e, g, nem1);
        }

        // Prefetch continuation window-1 indices if needed (n > 16).
        int k = s_cur + 16;
        Idx4 cc = { N_NODES_C, N_NODES_C, N_NODES_C, N_NODES_C };
        if (k < e_cur) cc = load_idx4(ci, k, e_cur, g, nem1);

        // Consume window 0.
        if (big0) consume_full(acc2, v0, v1, v2, v3);
        else      consume_half(acc2, v0, v1);

        // Continuation windows (pipelined: next window's idx loaded before
        // consuming the current one).
        while (k < e_cur) {
            const int rem = e_cur - k;
            const bool big = (rem > 8);
            uint4 w0 = __ldg(baseY + (size_t)cc.c0 * 8 + sub);
            uint4 w1 = __ldg(baseY + (size_t)cc.c1 * 8 + sub);
            uint4 w2 = make_uint4(0u, 0u, 0u, 0u);
            uint4 w3 = make_uint4(0u, 0u, 0u, 0u);
            if (big) {
                w2 = __ldg(baseY + (size_t)cc.c2 * 8 + sub);
                w3 = __ldg(baseY + (size_t)cc.c3 * 8 + sub);
            }
            const int k2 = k + 16;
            if (k2 < e_cur) cc = load_idx4(ci, k2, e_cur, g, nem1);
            if (big) consume_full(acc2, w0, w1, w2, w3);
            else     consume_half(acc2, w0, w1);
            k = k2;
        }

        // Reduce the 4 edge subgroups and store row.
        float a[8];
        #pragma unroll
        for (int i = 0; i < 4; i++) unpack2(acc2[i], a[2 * i], a[2 * i + 1]);
        #pragma unroll
        for (int q = 0; q < 8; q++) {
            a[q] += __shfl_xor_sync(0xffffffffu, a[q], 8);
            a[q] += __shfl_xor_sync(0xffffffffu, a[q], 16);
        }
        if (lane < 8) {
            float* op = out + (size_t)(base_row + j) * 64 + sub * 8;
            *(float4*)(op + 0) = make_float4(a[0], a[1], a[2], a[3]);
            *(float4*)(op + 4) = make_float4(a[4], a[5], a[6], a[7]);
        }

        c = nc;
    }
}

// ---------------------------------------------------------------------------
// kernel_launch
// Inputs: 0=X [100000,64] f32, 1=weights [64,64] f32, 2=row_pointers [100001] i32,
//         3=column_index [1600000] i32, 4..6 unused metadata.
// ---------------------------------------------------------------------------
extern "C" void kernel_launch(void* const* d_in, const int* in_sizes, int n_in,
                              void* d_out, int out_size)
{
    const float* X  = (const float*)d_in[0];
    const float* W  = (const float*)d_in[1];
    const int*   rp = (const int*)d_in[2];
    const int*   ci = (const int*)d_in[3];
    float*       out = (float*)d_out;

    const int M = in_sizes[0] / D_C;       // 100000
    const int NE = in_sizes[3];            // 1600000

    __half* Y;
    cudaGetSymbolAddress((void**)&Y, g_Yh);

    cudaFuncSetAttribute(gemm_tf32, cudaFuncAttributeMaxDynamicSharedMemorySize, SMEM_GEMM);
    {
        // grid covers rows 0..M inclusive (row M is the zero row)
        dim3 grid((M + 128) / 128);
        gemm_tf32<<<grid, 256, SMEM_GEMM>>>(X, W, Y, M);
    }
    {
        const int n_warps  = (M + ROWS_PER_WARP - 1) / ROWS_PER_WARP;   // 12500
        const int n_blocks = (n_warps + 3) / 4;                         // 3125
        spmm_agg_v6b<<<n_blocks, 128>>>(Y, rp, ci, out, NE);
    }
}